// round 7
// baseline (speedup 1.0000x reference)
#include <cuda_runtime.h>
#include <math.h>

// Problem constants
#define B_ 256
#define R_ 1152
#define C_ 10
#define O_ 16
#define I_ 8
#define RT_ 16              // r's per block
#define RCH_ (R_/RT_)       // 72 r-chunks -> grid 720 blocks, 5/SM, single wave

// ---------------- device scratch (no allocations allowed) ----------------
__device__ float g_xT[R_*B_*I_];       // x transposed: [r][b][i]   (9.4 MB)
__device__ float g_Wp[R_*C_*I_*O_];    // W reformatted: [r][c][i][o] (5.9 MB)
__device__ float g_b1[R_*C_*B_];       // routing logits b1: [r][c][b] (11.8 MB)
__device__ float g_S[C_*O_*B_];        // numerator accumulator: [c][o][b]
__device__ float g_E[C_*B_];           // softmax denominator:   [c][b]
__device__ float g_v[B_*C_*O_];        // squashed v: [b][c][o]

typedef unsigned long long u64;

// ---------------- packed f32x2 helpers (Blackwell FFMA2) ----------------
__device__ __forceinline__ u64 pk2(float lo, float hi){
    u64 r; asm("mov.b64 %0,{%1,%2};" : "=l"(r) : "f"(lo), "f"(hi)); return r;
}
__device__ __forceinline__ void upk2(u64 v, float& lo, float& hi){
    asm("mov.b64 {%0,%1},%2;" : "=f"(lo), "=f"(hi) : "l"(v));
}
__device__ __forceinline__ u64 ffma2(u64 a, u64 b, u64 c){
    u64 d; asm("fma.rn.f32x2 %0,%1,%2,%3;" : "=l"(d) : "l"(a), "l"(b), "l"(c)); return d;
}
__device__ __forceinline__ u64 fadd2(u64 a, u64 b){
    u64 d; asm("add.rn.f32x2 %0,%1,%2;" : "=l"(d) : "l"(a), "l"(b)); return d;
}

// ---------------- combined prep kernel ----------------
// blocks [0, 288): tiled transpose  xT[r][b][i] = x[b][r][i]  (coalesced both ways)
// blocks [288, 1008): Wp[r][c][i][o] = W[r][c][o][i]  + zero g_S/g_E
#define XT_BLOCKS 288            // 36 r-tiles x 8 b-tiles
#define PREP_BLOCKS (XT_BLOCKS + 720)

__global__ void __launch_bounds__(256) prep_kernel(const float* __restrict__ x,
                                                   const float* __restrict__ W){
    if (blockIdx.x < XT_BLOCKS){
        // 32r x 32b tile via padded smem planes (conflict-free LDS/STS.128)
        __shared__ __align__(16) float4 p0[32][33];
        __shared__ __align__(16) float4 p1[32][33];
        const int rt = blockIdx.x >> 3, bt = blockIdx.x & 7;
        const int r0 = rt*32, b0 = bt*32;
        const int w = threadIdx.x >> 5, lane = threadIdx.x & 31;

        // phase 1: per b-row, lanes cover 32 consecutive r (coalesced 1KB reads)
#pragma unroll
        for (int k = 0; k < 4; k++){
            int bl = w*4 + k;                         // 0..31
            const float4* src = reinterpret_cast<const float4*>(
                x + ((b0+bl)*R_ + r0 + lane)*I_);
            p0[bl][lane] = src[0];
            p1[bl][lane] = src[1];
        }
        __syncthreads();

        // phase 2: per r-row, lanes cover 32 consecutive b (coalesced 1KB writes)
#pragma unroll
        for (int k = 0; k < 4; k++){
            int rl = w*4 + k;
            float4* dst = reinterpret_cast<float4*>(
                g_xT + ((r0+rl)*B_ + b0 + lane)*I_);
            dst[0] = p0[lane][rl];
            dst[1] = p1[lane][rl];
        }
    } else {
        int t = (blockIdx.x - XT_BLOCKS)*256 + threadIdx.x;   // over R_*C_*O_ = 184320
        int o = t % O_; int rc = t / O_;
        const float* src = W + t*I_;                          // W[rc][o][0..7]
        float* dst = g_Wp + rc*(I_*O_);
#pragma unroll
        for (int i = 0; i < I_; i++) dst[i*O_ + o] = src[i];

        if (t < C_*O_*B_) g_S[t] = 0.f;
        if (t < C_*B_)    g_E[t] = 0.f;
    }
}

// ---------------- fused routing pass ----------------
// MODE 0: S += u_hat                        (uniform coupling, iteration 0)
// MODE 1: b1 = u.v0 (store), S += e*u, E += e,  e = exp(b1)
// MODE 2: b2 = b1 + u.v1,    S += e*u, E += e,  e = exp(b2)
// Block = (c, r-chunk of 16); 128 threads, each handles b = tid and b = tid+128.
// v lives in smem ([q][b] float4 layout -> conflict-free LDS.128) to keep regs <= 102
// so 5 blocks/SM stay resident: 720 blocks = ONE wave, 1.03 imbalance.
template<int MODE>
__global__ void __launch_bounds__(128, 5) pass_kernel(){
    __shared__ __align__(16) float Ws[RT_*I_*O_];     // 8 KB W slice for this c
    __shared__ __align__(16) float4 Vs[4][B_];        // 16 KB v slice (MODE>=1)
    const int c   = blockIdx.y;
    const int r0  = blockIdx.x * RT_;
    const int tid = threadIdx.x;
    const int b0  = tid;
    const int b1  = tid + 128;

    // cooperative W stage: RT_*32 float4 rows, 4 per thread
    for (int idx = tid; idx < RT_*32; idx += 128){
        int rl = idx >> 5, w = idx & 31;
        reinterpret_cast<float4*>(Ws)[idx] =
            reinterpret_cast<const float4*>(g_Wp)[((r0+rl)*C_ + c)*32 + w];
    }
    if (MODE){
        const float4* vpa = reinterpret_cast<const float4*>(g_v + (b0*C_ + c)*O_);
        const float4* vpb = reinterpret_cast<const float4*>(g_v + (b1*C_ + c)*O_);
#pragma unroll
        for (int q = 0; q < 4; q++){ Vs[q][b0] = vpa[q]; Vs[q][b1] = vpb[q]; }
    }
    __syncthreads();

    u64 Sa[8], Sb[8];
#pragma unroll
    for (int j = 0; j < 8; j++){ Sa[j] = 0ull; Sb[j] = 0ull; }
    float Ea = 0.f, Eb = 0.f;

#pragma unroll 1
    for (int rl = 0; rl < RT_; rl++){
        const int r = r0 + rl;
        // x loads first (coalesced 1KB per warp) so LDG latency overlaps the LDS below
        const float4* pa = reinterpret_cast<const float4*>(g_xT + (r*B_ + b0)*I_);
        const float4* pb = reinterpret_cast<const float4*>(g_xT + (r*B_ + b1)*I_);
        float4 xa0 = pa[0], xa1 = pa[1], xb0 = pb[0], xb1 = pb[1];
        const float xsa[8] = {xa0.x, xa0.y, xa0.z, xa0.w, xa1.x, xa1.y, xa1.z, xa1.w};
        const float xsb[8] = {xb0.x, xb0.y, xb0.z, xb0.w, xb1.x, xb1.y, xb1.z, xb1.w};

        u64 ua[8], ub[8];
#pragma unroll
        for (int j = 0; j < 8; j++){ ua[j] = 0ull; ub[j] = 0ull; }

        const float* wrow = Ws + rl*(I_*O_);
#pragma unroll
        for (int i = 0; i < I_; i++){
            u64 xda = pk2(xsa[i], xsa[i]);
            u64 xdb = pk2(xsb[i], xsb[i]);
            const ulonglong2* wp = reinterpret_cast<const ulonglong2*>(wrow + i*O_);
#pragma unroll
            for (int jj = 0; jj < 4; jj++){
                ulonglong2 ww = wp[jj];                 // LDS.128 broadcast, shared by both b's
                ua[2*jj]   = ffma2(ww.x, xda, ua[2*jj]);
                ua[2*jj+1] = ffma2(ww.y, xda, ua[2*jj+1]);
                ub[2*jj]   = ffma2(ww.x, xdb, ub[2*jj]);
                ub[2*jj+1] = ffma2(ww.y, xdb, ub[2*jj+1]);
            }
        }

        if (MODE == 0){
#pragma unroll
            for (int j = 0; j < 8; j++){
                Sa[j] = fadd2(Sa[j], ua[j]);
                Sb[j] = fadd2(Sb[j], ub[j]);
            }
        } else {
            // t = <u, v>, v from smem (4 independent chains)
            u64 t0 = 0ull, t1 = 0ull, t2 = 0ull, t3 = 0ull;
#pragma unroll
            for (int jj = 0; jj < 4; jj++){
                ulonglong2 va2 = *reinterpret_cast<const ulonglong2*>(&Vs[jj][b0]);
                ulonglong2 vb2 = *reinterpret_cast<const ulonglong2*>(&Vs[jj][b1]);
                t0 = ffma2(ua[2*jj],   va2.x, t0);
                t1 = ffma2(ua[2*jj+1], va2.y, t1);
                t2 = ffma2(ub[2*jj],   vb2.x, t2);
                t3 = ffma2(ub[2*jj+1], vb2.y, t3);
            }
            float l, h, ta, tb_;
            upk2(fadd2(t0, t1), l, h); ta  = l + h;
            upk2(fadd2(t2, t3), l, h); tb_ = l + h;

            const int bidx = (r*C_ + c)*B_ + b0;
            if (MODE == 2){ ta += g_b1[bidx]; tb_ += g_b1[bidx + 128]; }
            else          { g_b1[bidx] = ta;  g_b1[bidx + 128] = tb_;  }

            float ea = __expf(ta), eb = __expf(tb_);
            Ea += ea; Eb += eb;
            u64 eda = pk2(ea, ea), edb = pk2(eb, eb);
#pragma unroll
            for (int j = 0; j < 8; j++){
                Sa[j] = ffma2(ua[j], eda, Sa[j]);
                Sb[j] = ffma2(ub[j], edb, Sb[j]);
            }
        }
    }

    // one coalesced flush per block (distinct addresses per lane)
#pragma unroll
    for (int j = 0; j < 8; j++){
        float lo, hi;
        upk2(Sa[j], lo, hi);
        atomicAdd(&g_S[(c*O_ + 2*j    )*B_ + b0], lo);
        atomicAdd(&g_S[(c*O_ + 2*j + 1)*B_ + b0], hi);
        upk2(Sb[j], lo, hi);
        atomicAdd(&g_S[(c*O_ + 2*j    )*B_ + b1], lo);
        atomicAdd(&g_S[(c*O_ + 2*j + 1)*B_ + b1], hi);
    }
    if (MODE){
        atomicAdd(&g_E[c*B_ + b0], Ea);
        atomicAdd(&g_E[c*B_ + b1], Eb);
    }
}

// ---------------- squash (+ normalization + accumulator re-zero) ----------------
// block = c (grid 10), lane = b: every g_S access coalesced, o-reduction in regs.
// mode 0: s = S / R   (uniform coupling); mode 1: s = S / E (softmax-normalized)
__global__ void __launch_bounds__(256) squash_kernel(float* out, int mode){
    const int c = blockIdx.x;
    const int b = threadIdx.x;

    float s[O_];
    float inv;
    if (mode){ inv = 1.0f / g_E[c*B_ + b]; g_E[c*B_ + b] = 0.f; }
    else     { inv = 1.0f / (float)R_; }

    float sq = 0.f;
#pragma unroll
    for (int o = 0; o < O_; o++){
        int sidx = (c*O_ + o)*B_ + b;          // coalesced across lanes
        float v = g_S[sidx] * inv;
        g_S[sidx] = 0.f;                        // re-zero for next pass / replay
        s[o] = v;
        sq += v*v;
    }

    float scale = sq / ((1.0f + sq) * sqrtf(sq + 1e-7f));
    float* dst = (out ? out : g_v) + (b*C_ + c)*O_;
    float4* d4 = reinterpret_cast<float4*>(dst);
#pragma unroll
    for (int q = 0; q < 4; q++)
        d4[q] = make_float4(s[4*q]*scale, s[4*q+1]*scale, s[4*q+2]*scale, s[4*q+3]*scale);
}

// ---------------- launch ----------------
extern "C" void kernel_launch(void* const* d_in, const int* in_sizes, int n_in,
                              void* d_out, int out_size){
    const float* x = (const float*)d_in[0];
    const float* W = (const float*)d_in[1];
    // defensive: identify by size (x has 2359296 elems, W has 1474560)
    if (n_in >= 2 && in_sizes[0] == R_*C_*O_*I_){ const float* t = x; x = W; W = t; }

    prep_kernel<<<PREP_BLOCKS, 256>>>(x, W);   // transpose x, reformat W, zero S/E

    dim3 grid(RCH_, C_);
    pass_kernel<0><<<grid, 128>>>();
    squash_kernel<<<C_, 256>>>(nullptr, 0);          // v0
    pass_kernel<1><<<grid, 128>>>();
    squash_kernel<<<C_, 256>>>(nullptr, 1);          // v1
    pass_kernel<2><<<grid, 128>>>();
    squash_kernel<<<C_, 256>>>((float*)d_out, 1);    // v2 -> output (B,1,C,O,1)
}

// round 8
// speedup vs baseline: 1.1300x; 1.1300x over previous
#include <cuda_runtime.h>
#include <math.h>

// Problem constants
#define B_ 256
#define R_ 1152
#define C_ 10
#define O_ 16
#define I_ 8
#define RT_ 4                 // r's per tile
#define RPC_ (R_/RT_)         // 288 tiles per c
#define NT_ (RPC_*C_)         // 2880 tiles total
#define G_ 444                // persistent blocks = 148 SMs x 3 -> ONE wave

// ---------------- device scratch (no allocations allowed) ----------------
__device__ float g_xT[R_*B_*I_];       // x transposed: [r][b][i]   (9.4 MB)
__device__ float g_Wp[R_*C_*I_*O_];    // W reformatted: [r][c][i][o] (5.9 MB)
__device__ float g_b1[R_*C_*B_];       // routing logits b1: [r][c][b] (11.8 MB)
__device__ float g_S[C_*O_*B_];        // numerator accumulator: [c][o][b]
__device__ float g_E[C_*B_];           // softmax denominator:   [c][b]
__device__ float g_v[B_*C_*O_];        // squashed v: [b][c][o]

typedef unsigned long long u64;

// ---------------- packed f32x2 helpers (Blackwell FFMA2) ----------------
__device__ __forceinline__ u64 pk2(float lo, float hi){
    u64 r; asm("mov.b64 %0,{%1,%2};" : "=l"(r) : "f"(lo), "f"(hi)); return r;
}
__device__ __forceinline__ void upk2(u64 v, float& lo, float& hi){
    asm("mov.b64 {%0,%1},%2;" : "=f"(lo), "=f"(hi) : "l"(v));
}
__device__ __forceinline__ u64 ffma2(u64 a, u64 b, u64 c){
    u64 d; asm("fma.rn.f32x2 %0,%1,%2,%3;" : "=l"(d) : "l"(a), "l"(b), "l"(c)); return d;
}
__device__ __forceinline__ u64 fadd2(u64 a, u64 b){
    u64 d; asm("add.rn.f32x2 %0,%1,%2;" : "=l"(d) : "l"(a), "l"(b)); return d;
}

// ---------------- combined prep kernel ----------------
// blocks [0, 288): tiled transpose  xT[r][b][i] = x[b][r][i]  (coalesced both ways)
// blocks [288, 1008): Wp[r][c][i][o] = W[r][c][o][i]  + zero g_S/g_E
#define XT_BLOCKS 288            // 36 r-tiles x 8 b-tiles
#define PREP_BLOCKS (XT_BLOCKS + 720)

__global__ void __launch_bounds__(256) prep_kernel(const float* __restrict__ x,
                                                   const float* __restrict__ W){
    if (blockIdx.x < XT_BLOCKS){
        __shared__ __align__(16) float4 p0[32][33];
        __shared__ __align__(16) float4 p1[32][33];
        const int rt = blockIdx.x >> 3, bt = blockIdx.x & 7;
        const int r0 = rt*32, b0 = bt*32;
        const int w = threadIdx.x >> 5, lane = threadIdx.x & 31;

#pragma unroll
        for (int k = 0; k < 4; k++){
            int bl = w*4 + k;
            const float4* src = reinterpret_cast<const float4*>(
                x + ((b0+bl)*R_ + r0 + lane)*I_);
            p0[bl][lane] = src[0];
            p1[bl][lane] = src[1];
        }
        __syncthreads();
#pragma unroll
        for (int k = 0; k < 4; k++){
            int rl = w*4 + k;
            float4* dst = reinterpret_cast<float4*>(
                g_xT + ((r0+rl)*B_ + b0 + lane)*I_);
            dst[0] = p0[lane][rl];
            dst[1] = p1[lane][rl];
        }
    } else {
        int t = (blockIdx.x - XT_BLOCKS)*256 + threadIdx.x;   // over R_*C_*O_
        int o = t % O_; int rc = t / O_;
        const float* src = W + t*I_;                          // W[rc][o][0..7]
        float* dst = g_Wp + rc*(I_*O_);
#pragma unroll
        for (int i = 0; i < I_; i++) dst[i*O_ + o] = src[i];

        if (t < C_*O_*B_) g_S[t] = 0.f;
        if (t < C_*B_)    g_E[t] = 0.f;
    }
}

// ---------------- fused routing pass (persistent blocks) ----------------
// MODE 0: S += u_hat
// MODE 1: b1 = u.v0 (store), S += e*u, E += e,  e = exp(b1)
// MODE 2: b2 = b1 + u.v1,    S += e*u, E += e,  e = exp(b2)
// 444 persistent blocks, 128 threads, each thread handles b=tid and b=tid+128.
// Tiles (c-major, RT=4 r's) split contiguously: balance 1.08, one wave exactly.
// S kept in registers across tiles of the same c; flushed on c-change/end.

__device__ __forceinline__ void flush_S(int c, int b0, int b1,
                                        const u64* Sa, const u64* Sb,
                                        float Ea, float Eb, int mode){
#pragma unroll
    for (int j = 0; j < 8; j++){
        float lo, hi;
        upk2(Sa[j], lo, hi);
        atomicAdd(&g_S[(c*O_ + 2*j    )*B_ + b0], lo);
        atomicAdd(&g_S[(c*O_ + 2*j + 1)*B_ + b0], hi);
        upk2(Sb[j], lo, hi);
        atomicAdd(&g_S[(c*O_ + 2*j    )*B_ + b1], lo);
        atomicAdd(&g_S[(c*O_ + 2*j + 1)*B_ + b1], hi);
    }
    if (mode){
        atomicAdd(&g_E[c*B_ + b0], Ea);
        atomicAdd(&g_E[c*B_ + b1], Eb);
    }
}

template<int MODE>
__global__ void __launch_bounds__(128, 3) pass_kernel(){
    __shared__ __align__(16) float4 Ws[2][RT_*32];   // double-buffered W tile (2x2KB)
    const int k   = blockIdx.x;
    const int t0  = (k    * NT_) / G_;
    const int t1  = ((k+1)* NT_) / G_;
    const int tid = threadIdx.x;
    const int b0  = tid;
    const int b1  = tid + 128;
    const int srl = tid >> 5, sw = tid & 31;         // this thread's stage slot

    u64 Sa[8], Sb[8], va[8], vb[8];
    float Ea = 0.f, Eb = 0.f;
    int cur_c = -1;
    int p = 0;

#pragma unroll 1
    for (int t = t0; t < t1; t++){
        const int c  = t / RPC_;
        const int r0 = (t % RPC_) * RT_;

        if (c != cur_c){
            if (cur_c >= 0) flush_S(cur_c, b0, b1, Sa, Sb, Ea, Eb, MODE);
#pragma unroll
            for (int j = 0; j < 8; j++){ Sa[j] = 0ull; Sb[j] = 0ull; }
            Ea = 0.f; Eb = 0.f;
            if (MODE){
                const float4* vpa = reinterpret_cast<const float4*>(g_v + (b0*C_ + c)*O_);
                const float4* vpb = reinterpret_cast<const float4*>(g_v + (b1*C_ + c)*O_);
#pragma unroll
                for (int q = 0; q < 4; q++){
                    float4 f = vpa[q]; va[2*q] = pk2(f.x, f.y); va[2*q+1] = pk2(f.z, f.w);
                    float4 g = vpb[q]; vb[2*q] = pk2(g.x, g.y); vb[2*q+1] = pk2(g.z, g.w);
                }
            }
            cur_c = c;
        }

        // stage this tile's W (1 float4 per thread) into buffer p
        Ws[p][srl*32 + sw] =
            reinterpret_cast<const float4*>(g_Wp)[((r0+srl)*C_ + c)*32 + sw];

        // preload x for rl=0 (overlaps the stage)
        float4 nxa0, nxa1, nxb0, nxb1;
        {
            const float4* pa = reinterpret_cast<const float4*>(g_xT + (r0*B_ + b0)*I_);
            const float4* pb = reinterpret_cast<const float4*>(g_xT + (r0*B_ + b1)*I_);
            nxa0 = pa[0]; nxa1 = pa[1]; nxb0 = pb[0]; nxb1 = pb[1];
        }
        __syncthreads();                              // one sync per tile

#pragma unroll
        for (int rl = 0; rl < RT_; rl++){
            const float xsa[8] = {nxa0.x, nxa0.y, nxa0.z, nxa0.w, nxa1.x, nxa1.y, nxa1.z, nxa1.w};
            const float xsb[8] = {nxb0.x, nxb0.y, nxb0.z, nxb0.w, nxb1.x, nxb1.y, nxb1.z, nxb1.w};

            if (rl + 1 < RT_){                        // prefetch next rl's x
                const float4* pa = reinterpret_cast<const float4*>(g_xT + ((r0+rl+1)*B_ + b0)*I_);
                const float4* pb = reinterpret_cast<const float4*>(g_xT + ((r0+rl+1)*B_ + b1)*I_);
                nxa0 = pa[0]; nxa1 = pa[1]; nxb0 = pb[0]; nxb1 = pb[1];
            }

            u64 ua[8], ub[8];
#pragma unroll
            for (int j = 0; j < 8; j++){ ua[j] = 0ull; ub[j] = 0ull; }

            const float* wrow = reinterpret_cast<const float*>(&Ws[p][rl*32]);
#pragma unroll
            for (int i = 0; i < I_; i++){
                u64 xda = pk2(xsa[i], xsa[i]);
                u64 xdb = pk2(xsb[i], xsb[i]);
                const ulonglong2* wp = reinterpret_cast<const ulonglong2*>(wrow + i*O_);
#pragma unroll
                for (int jj = 0; jj < 4; jj++){
                    ulonglong2 ww = wp[jj];           // LDS.128 broadcast, shared by both b's
                    ua[2*jj]   = ffma2(ww.x, xda, ua[2*jj]);
                    ua[2*jj+1] = ffma2(ww.y, xda, ua[2*jj+1]);
                    ub[2*jj]   = ffma2(ww.x, xdb, ub[2*jj]);
                    ub[2*jj+1] = ffma2(ww.y, xdb, ub[2*jj+1]);
                }
            }

            if (MODE == 0){
#pragma unroll
                for (int j = 0; j < 8; j++){
                    Sa[j] = fadd2(Sa[j], ua[j]);
                    Sb[j] = fadd2(Sb[j], ub[j]);
                }
            } else {
                u64 t0_ = 0ull, t1_ = 0ull, t2_ = 0ull, t3_ = 0ull;
#pragma unroll
                for (int j = 0; j < 4; j++){
                    t0_ = ffma2(ua[2*j],   va[2*j],   t0_);
                    t1_ = ffma2(ua[2*j+1], va[2*j+1], t1_);
                    t2_ = ffma2(ub[2*j],   vb[2*j],   t2_);
                    t3_ = ffma2(ub[2*j+1], vb[2*j+1], t3_);
                }
                float l, h, ta, tb_;
                upk2(fadd2(t0_, t1_), l, h); ta  = l + h;
                upk2(fadd2(t2_, t3_), l, h); tb_ = l + h;

                const int r = r0 + rl;
                const int bidx = (r*C_ + c)*B_ + b0;
                if (MODE == 2){ ta += g_b1[bidx]; tb_ += g_b1[bidx + 128]; }
                else          { g_b1[bidx] = ta;  g_b1[bidx + 128] = tb_;  }

                float ea = __expf(ta), eb = __expf(tb_);
                Ea += ea; Eb += eb;
                u64 eda = pk2(ea, ea), edb = pk2(eb, eb);
#pragma unroll
                for (int j = 0; j < 8; j++){
                    Sa[j] = ffma2(ua[j], eda, Sa[j]);
                    Sb[j] = ffma2(ub[j], edb, Sb[j]);
                }
            }
        }
        p ^= 1;
    }
    if (cur_c >= 0) flush_S(cur_c, b0, b1, Sa, Sb, Ea, Eb, MODE);
}

// ---------------- squash (+ normalization + accumulator re-zero) ----------------
// grid (C_, 2), 128 threads: lane = b-half; all g_S accesses coalesced.
__global__ void __launch_bounds__(128) squash_kernel(float* out, int mode){
    const int c = blockIdx.x;
    const int b = blockIdx.y*128 + threadIdx.x;

    float s[O_];
    float inv;
    if (mode){ inv = 1.0f / g_E[c*B_ + b]; g_E[c*B_ + b] = 0.f; }
    else     { inv = 1.0f / (float)R_; }

    float sq = 0.f;
#pragma unroll
    for (int o = 0; o < O_; o++){
        int sidx = (c*O_ + o)*B_ + b;
        float v = g_S[sidx] * inv;
        g_S[sidx] = 0.f;                  // re-zero for next pass / replay
        s[o] = v;
        sq += v*v;
    }

    float scale = sq / ((1.0f + sq) * sqrtf(sq + 1e-7f));
    float* dst = (out ? out : g_v) + (b*C_ + c)*O_;
    float4* d4 = reinterpret_cast<float4*>(dst);
#pragma unroll
    for (int q = 0; q < 4; q++)
        d4[q] = make_float4(s[4*q]*scale, s[4*q+1]*scale, s[4*q+2]*scale, s[4*q+3]*scale);
}

// ---------------- launch ----------------
extern "C" void kernel_launch(void* const* d_in, const int* in_sizes, int n_in,
                              void* d_out, int out_size){
    const float* x = (const float*)d_in[0];
    const float* W = (const float*)d_in[1];
    if (n_in >= 2 && in_sizes[0] == R_*C_*O_*I_){ const float* t = x; x = W; W = t; }

    prep_kernel<<<PREP_BLOCKS, 256>>>(x, W);   // transpose x, reformat W, zero S/E

    dim3 sq_grid(C_, 2);
    pass_kernel<0><<<G_, 128>>>();
    squash_kernel<<<sq_grid, 128>>>(nullptr, 0);          // v0
    pass_kernel<1><<<G_, 128>>>();
    squash_kernel<<<sq_grid, 128>>>(nullptr, 1);          // v1
    pass_kernel<2><<<G_, 128>>>();
    squash_kernel<<<sq_grid, 128>>>((float*)d_out, 1);    // v2 -> output (B,1,C,O,1)
}